// round 14
// baseline (speedup 1.0000x reference)
#include <cuda_runtime.h>
#include <cuda_bf16.h>
#include <math.h>
#include <stdint.h>

#define BATCH 8
#define NN    4096
#define EE    1024
#define CC    512

typedef __nv_bfloat16 bf16;

// ---- scratch (device globals: allocation-free) ----
__device__ bf16  g_Nhi [(size_t)BATCH * NN * CC];
__device__ bf16  g_Nlo [(size_t)BATCH * NN * CC];
__device__ bf16  g_Hhi [(size_t)BATCH * EE * CC];
__device__ bf16  g_Hlo [(size_t)BATCH * EE * CC];
__device__ bf16  g_Wqhi[(size_t)CC * CC];
__device__ bf16  g_Wqlo[(size_t)CC * CC];
__device__ bf16  g_Wkhi[(size_t)2 * CC * CC];
__device__ bf16  g_Wklo[(size_t)2 * CC * CC];
__device__ bf16  g_Qhi [(size_t)BATCH * NN * CC];
__device__ bf16  g_Qlo [(size_t)BATCH * NN * CC];
__device__ bf16  g_KVhi[(size_t)BATCH * EE * 2 * CC];
__device__ bf16  g_KVlo[(size_t)BATCH * EE * 2 * CC];
__device__ bf16  g_Vthi[(size_t)BATCH * CC * EE];
__device__ bf16  g_Vtlo[(size_t)BATCH * CC * EE];
__device__ bf16  g_Shi [(size_t)BATCH * NN * EE];      // 64 MB (logits hi)
__device__ bf16  g_Slo [(size_t)BATCH * NN * EE];      // 64 MB (logits lo)
__device__ bf16  g_Phi [(size_t)BATCH * NN * EE];
__device__ bf16  g_Plo [(size_t)BATCH * NN * EE];

// ============================================================================
// helpers
// ============================================================================
static __device__ __forceinline__ uint32_t smem_u32(const void* p) {
    uint32_t a;
    asm("{ .reg .u64 t; cvta.to.shared.u64 t, %1; cvt.u32.u64 %0, t; }" : "=r"(a) : "l"(p));
    return a;
}
static __device__ __forceinline__ void mma_bf16(float* d, const uint32_t* a, const uint32_t* b) {
    asm volatile(
        "mma.sync.aligned.m16n8k16.row.col.f32.bf16.bf16.f32 "
        "{%0,%1,%2,%3}, {%4,%5,%6,%7}, {%8,%9}, {%0,%1,%2,%3};"
        : "+f"(d[0]), "+f"(d[1]), "+f"(d[2]), "+f"(d[3])
        : "r"(a[0]), "r"(a[1]), "r"(a[2]), "r"(a[3]), "r"(b[0]), "r"(b[1]));
}
static __device__ __forceinline__ void ldsm4(uint32_t* r, uint32_t addr) {
    asm volatile("ldmatrix.sync.aligned.m8n8.x4.shared.b16 {%0,%1,%2,%3}, [%4];"
        : "=r"(r[0]), "=r"(r[1]), "=r"(r[2]), "=r"(r[3]) : "r"(addr));
}
static __device__ __forceinline__ void split2(float x, float y, uint32_t& hi, uint32_t& lo) {
    bf16 hx = __float2bfloat16(x), hy = __float2bfloat16(y);
    __nv_bfloat162 h; h.x = hx; h.y = hy;
    __nv_bfloat162 l;
    l.x = __float2bfloat16(x - __bfloat162float(hx));
    l.y = __float2bfloat16(y - __bfloat162float(hy));
    hi = *reinterpret_cast<uint32_t*>(&h);
    lo = *reinterpret_cast<uint32_t*>(&l);
}
static __device__ __forceinline__ void cp16(uint32_t dst, const void* src) {
    asm volatile("cp.async.cg.shared.global [%0], [%1], 16;" :: "r"(dst), "l"(src));
}
static __device__ __forceinline__ void cp_commit() {
    asm volatile("cp.async.commit_group;" ::: "memory");
}
static __device__ __forceinline__ void cp_wait1() {
    asm volatile("cp.async.wait_group 1;" ::: "memory");
}

// ============================================================================
// elementwise fp32 -> bf16 hi/lo split (vectorized by 4)
// ============================================================================
__global__ __launch_bounds__(256) void split_f32(
    const float* __restrict__ x, bf16* __restrict__ hi, bf16* __restrict__ lo, int n4)
{
    int t = blockIdx.x * blockDim.x + threadIdx.x;
    if (t >= n4) return;
    float4 v = ((const float4*)x)[t];
    uint2 h, l;
    split2(v.x, v.y, h.x, l.x);
    split2(v.z, v.w, h.y, l.y);
    ((uint2*)hi)[t] = h;
    ((uint2*)lo)[t] = l;
}

// ============================================================================
// Tensor-core NT GEMM, pre-split bf16 hi/lo operands, 3-pass, fp32 acc:
//   C[m,n] = alpha * sum_k A[m,k]*B[n,k] + bias[n]
// Tile 128x128x32, 512 threads (16 warps 4x4, warp tile 32x32).
// 3-stage cp.async pipeline. Output: fp32 (Cf) or bf16 hi/lo (Chi/Clo).
// ============================================================================
#define ROWB    80
#define ARR_SZ  (128 * ROWB)       // 10240
#define STG_SZ  (4 * ARR_SZ)       // 40960
#define NSTAGE  3
#define SMEM_T  (NSTAGE * STG_SZ)  // 122880

__global__ __launch_bounds__(512) void tc_gemm_bf(
    const bf16* __restrict__ Ahi, const bf16* __restrict__ Alo,
    const bf16* __restrict__ Bhi, const bf16* __restrict__ Blo,
    const float* __restrict__ bias,
    float* __restrict__ Cf, bf16* __restrict__ Chi, bf16* __restrict__ Clo,
    int K, int lda, int ldb, int ldc,
    size_t sA, size_t sB, size_t sC, float alpha)
{
    extern __shared__ __align__(16) unsigned char sm[];
    const uint32_t sb = smem_u32(sm);

    Ahi += (size_t)blockIdx.z * sA;  Alo += (size_t)blockIdx.z * sA;
    Bhi += (size_t)blockIdx.z * sB;  Blo += (size_t)blockIdx.z * sB;
    if (Cf)  Cf  += (size_t)blockIdx.z * sC;
    if (Chi) Chi += (size_t)blockIdx.z * sC;
    if (Clo) Clo += (size_t)blockIdx.z * sC;

    const int bm = blockIdx.y * 128;
    const int bn = blockIdx.x * 128;

    const int tid  = threadIdx.x;
    const int wid  = tid >> 5;
    const int lane = tid & 31;
    const int warp_m = (wid >> 2) * 32;
    const int warp_n = (wid & 3) * 32;

    // gmem load mapping: 4 threads per 128-row, each thread one uint4 (8 bf16)
    const int lrow = tid >> 2;             // 0..127
    const int lq   = tid & 3;              // 0..3
    const bf16* pAh = Ahi + (size_t)(bm + lrow) * lda + lq * 8;
    const bf16* pAl = Alo + (size_t)(bm + lrow) * lda + lq * 8;
    const bf16* pBh = Bhi + (size_t)(bn + lrow) * ldb + lq * 8;
    const bf16* pBl = Blo + (size_t)(bn + lrow) * ldb + lq * 8;
    const uint32_t st_off = (uint32_t)(lrow * ROWB + lq * 16);

    const uint32_t lm_row  = (uint32_t)(lane & 15);
    const uint32_t lm_koff = (uint32_t)((lane >> 4) * 16);

    float acc[2][4][4];
    #pragma unroll
    for (int i = 0; i < 2; i++)
        #pragma unroll
        for (int j = 0; j < 4; j++)
            #pragma unroll
            for (int q = 0; q < 4; q++) acc[i][j][q] = 0.0f;

    auto cpa = [&](int st, int k0) {
        const uint32_t base = sb + (uint32_t)(st * STG_SZ) + st_off;
        cp16(base + 0 * ARR_SZ, pAh + k0);
        cp16(base + 1 * ARR_SZ, pAl + k0);
        cp16(base + 2 * ARR_SZ, pBh + k0);
        cp16(base + 3 * ARR_SZ, pBl + k0);
    };
    auto compute = [&](int st) {
        const uint32_t base = sb + (uint32_t)(st * STG_SZ);
        #pragma unroll
        for (int ks = 0; ks < 2; ks++) {
            const uint32_t kb = (uint32_t)(ks * 32) + lm_koff;
            uint32_t aHi[2][4], aLo[2][4];
            #pragma unroll
            for (int am = 0; am < 2; am++) {
                const uint32_t ro = (uint32_t)(warp_m + am * 16) + lm_row;
                ldsm4(aHi[am], base + 0 * ARR_SZ + ro * ROWB + kb);
                ldsm4(aLo[am], base + 1 * ARR_SZ + ro * ROWB + kb);
            }
            uint32_t bHi[4][2], bLo[4][2];
            #pragma unroll
            for (int bg = 0; bg < 2; bg++) {
                const uint32_t ro = (uint32_t)(warp_n + bg * 16) + lm_row;
                uint32_t r[4];
                ldsm4(r, base + 2 * ARR_SZ + ro * ROWB + kb);
                bHi[bg * 2 + 0][0] = r[0]; bHi[bg * 2 + 0][1] = r[2];
                bHi[bg * 2 + 1][0] = r[1]; bHi[bg * 2 + 1][1] = r[3];
                ldsm4(r, base + 3 * ARR_SZ + ro * ROWB + kb);
                bLo[bg * 2 + 0][0] = r[0]; bLo[bg * 2 + 0][1] = r[2];
                bLo[bg * 2 + 1][0] = r[1]; bLo[bg * 2 + 1][1] = r[3];
            }
            #pragma unroll
            for (int am = 0; am < 2; am++)
                #pragma unroll
                for (int an = 0; an < 4; an++) {
                    mma_bf16(acc[am][an], aHi[am], bHi[an]);
                    mma_bf16(acc[am][an], aHi[am], bLo[an]);
                    mma_bf16(acc[am][an], aLo[am], bHi[an]);
                }
        }
    };

    const int nch = K >> 5;    // >= 16 for all our shapes
    cpa(0, 0);        cp_commit();
    cpa(1, 32);       cp_commit();
    int st = 0;
    for (int c = 0; c < nch; c++) {
        cp_wait1();
        __syncthreads();
        const int nk = c + NSTAGE - 1;
        if (nk < nch) {
            int nst = st + NSTAGE - 1; if (nst >= NSTAGE) nst -= NSTAGE;
            cpa(nst, nk << 5);
        }
        cp_commit();
        compute(st);
        if (++st == NSTAGE) st = 0;
    }

    // ---- epilogue ----
    const bool hb = (bias != nullptr);
    #pragma unroll
    for (int am = 0; am < 2; am++) {
        #pragma unroll
        for (int an = 0; an < 4; an++) {
            const int col = bn + warp_n + an * 8 + (lane & 3) * 2;
            float bx = 0.f, by = 0.f;
            if (hb) { bx = __ldg(&bias[col]); by = __ldg(&bias[col + 1]); }
            const int r0 = bm + warp_m + am * 16 + (lane >> 2);
            float v0x = acc[am][an][0] * alpha + bx;
            float v0y = acc[am][an][1] * alpha + by;
            float v1x = acc[am][an][2] * alpha + bx;
            float v1y = acc[am][an][3] * alpha + by;
            if (Cf) {
                *(float2*)&Cf[(size_t)r0 * ldc + col]       = make_float2(v0x, v0y);
                *(float2*)&Cf[(size_t)(r0 + 8) * ldc + col] = make_float2(v1x, v1y);
            } else {
                uint32_t h0, l0, h1, l1;
                split2(v0x, v0y, h0, l0);
                split2(v1x, v1y, h1, l1);
                *(uint32_t*)&Chi[(size_t)r0 * ldc + col]       = h0;
                *(uint32_t*)&Clo[(size_t)r0 * ldc + col]       = l0;
                *(uint32_t*)&Chi[(size_t)(r0 + 8) * ldc + col] = h1;
                *(uint32_t*)&Clo[(size_t)(r0 + 8) * ldc + col] = l1;
            }
        }
    }
}

// ============================================================================
// Transpose V half of KV (bf16 hi/lo) into Vt[b][c][e]
// ============================================================================
__global__ void transpose_v_bf(const bf16* __restrict__ KVhi, const bf16* __restrict__ KVlo,
                               bf16* __restrict__ Vthi, bf16* __restrict__ Vtlo)
{
    __shared__ bf16 th[32][33];
    __shared__ bf16 tl[32][33];
    const int b  = blockIdx.z;
    const int e0 = blockIdx.x * 32;
    const int c0 = blockIdx.y * 32;
    const int tx = threadIdx.x;
    const int ty = threadIdx.y;

    #pragma unroll
    for (int i = 0; i < 32; i += 8) {
        size_t idx = ((size_t)b * EE + e0 + ty + i) * (2 * CC) + CC + c0 + tx;
        th[ty + i][tx] = KVhi[idx];
        tl[ty + i][tx] = KVlo[idx];
    }
    __syncthreads();
    #pragma unroll
    for (int i = 0; i < 32; i += 8) {
        size_t idx = ((size_t)b * CC + c0 + ty + i) * EE + e0 + tx;
        Vthi[idx] = th[tx][ty + i];
        Vtlo[idx] = tl[tx][ty + i];
    }
}

// ============================================================================
// Row softmax over E=1024 on bf16 hi/lo logits, outputs bf16 hi/lo P.
// ============================================================================
__global__ __launch_bounds__(256) void softmax_rows(
    const bf16* __restrict__ Shi, const bf16* __restrict__ Slo,
    bf16* __restrict__ Phi, bf16* __restrict__ Plo)
{
    __shared__ float red[32];
    const size_t row = blockIdx.x;
    const int t = threadIdx.x;

    uint2 hr = ((const uint2*)(Shi + row * (size_t)EE))[t];
    uint2 lr = ((const uint2*)(Slo + row * (size_t)EE))[t];
    __nv_bfloat162 h01 = *reinterpret_cast<__nv_bfloat162*>(&hr.x);
    __nv_bfloat162 h23 = *reinterpret_cast<__nv_bfloat162*>(&hr.y);
    __nv_bfloat162 l01 = *reinterpret_cast<__nv_bfloat162*>(&lr.x);
    __nv_bfloat162 l23 = *reinterpret_cast<__nv_bfloat162*>(&lr.y);
    float4 v;
    v.x = __bfloat162float(h01.x) + __bfloat162float(l01.x);
    v.y = __bfloat162float(h01.y) + __bfloat162float(l01.y);
    v.z = __bfloat162float(h23.x) + __bfloat162float(l23.x);
    v.w = __bfloat162float(h23.y) + __bfloat162float(l23.y);

    float m = fmaxf(fmaxf(v.x, v.y), fmaxf(v.z, v.w));
    #pragma unroll
    for (int o = 16; o; o >>= 1) m = fmaxf(m, __shfl_xor_sync(0xffffffffu, m, o));
    if ((t & 31) == 0) red[t >> 5] = m;
    __syncthreads();
    if (t < 32) {
        float x = (t < 8) ? red[t] : -INFINITY;
        #pragma unroll
        for (int o = 4; o; o >>= 1) x = fmaxf(x, __shfl_xor_sync(0xffffffffu, x, o));
        if (t == 0) red[0] = x;
    }
    __syncthreads();
    m = red[0];
    __syncthreads();

    v.x = __expf(v.x - m); v.y = __expf(v.y - m);
    v.z = __expf(v.z - m); v.w = __expf(v.w - m);
    float s = v.x + v.y + v.z + v.w;
    #pragma unroll
    for (int o = 16; o; o >>= 1) s += __shfl_xor_sync(0xffffffffu, s, o);
    if ((t & 31) == 0) red[t >> 5] = s;
    __syncthreads();
    if (t < 32) {
        float x = (t < 8) ? red[t] : 0.0f;
        #pragma unroll
        for (int o = 4; o; o >>= 1) x += __shfl_xor_sync(0xffffffffu, x, o);
        if (t == 0) red[0] = x;
    }
    __syncthreads();
    const float inv = 1.0f / red[0];

    v.x *= inv; v.y *= inv; v.z *= inv; v.w *= inv;
    uint2 h, l;
    split2(v.x, v.y, h.x, l.x);
    split2(v.z, v.w, h.y, l.y);
    ((uint2*)(Phi + row * (size_t)EE))[t] = h;
    ((uint2*)(Plo + row * (size_t)EE))[t] = l;
}

// ============================================================================
// launch
// ============================================================================
extern "C" void kernel_launch(void* const* d_in, const int* in_sizes, int n_in,
                              void* d_out, int out_size)
{
    const float* node  = (const float*)d_in[0];
    const float* hyper = (const float*)d_in[1];
    const float* Wq    = (const float*)d_in[2];
    const float* bq    = (const float*)d_in[3];
    const float* Wkv   = (const float*)d_in[4];
    const float* bkv   = (const float*)d_in[5];
    float* out = (float*)d_out;

    bf16 *pNhi, *pNlo, *pHhi, *pHlo, *pWqhi, *pWqlo, *pWkhi, *pWklo;
    bf16 *pQhi, *pQlo, *pKVhi, *pKVlo, *pVthi, *pVtlo, *pPhi, *pPlo;
    bf16 *pShi, *pSlo;
    cudaGetSymbolAddress((void**)&pNhi,  g_Nhi);  cudaGetSymbolAddress((void**)&pNlo,  g_Nlo);
    cudaGetSymbolAddress((void**)&pHhi,  g_Hhi);  cudaGetSymbolAddress((void**)&pHlo,  g_Hlo);
    cudaGetSymbolAddress((void**)&pWqhi, g_Wqhi); cudaGetSymbolAddress((void**)&pWqlo, g_Wqlo);
    cudaGetSymbolAddress((void**)&pWkhi, g_Wkhi); cudaGetSymbolAddress((void**)&pWklo, g_Wklo);
    cudaGetSymbolAddress((void**)&pQhi,  g_Qhi);  cudaGetSymbolAddress((void**)&pQlo,  g_Qlo);
    cudaGetSymbolAddress((void**)&pKVhi, g_KVhi); cudaGetSymbolAddress((void**)&pKVlo, g_KVlo);
    cudaGetSymbolAddress((void**)&pVthi, g_Vthi); cudaGetSymbolAddress((void**)&pVtlo, g_Vtlo);
    cudaGetSymbolAddress((void**)&pPhi,  g_Phi);  cudaGetSymbolAddress((void**)&pPlo,  g_Plo);
    cudaGetSymbolAddress((void**)&pShi,  g_Shi);  cudaGetSymbolAddress((void**)&pSlo,  g_Slo);

    cudaFuncSetAttribute(tc_gemm_bf, cudaFuncAttributeMaxDynamicSharedMemorySize, SMEM_T);

    const float scale = 0.04419417382415922f;  // 512^-0.5

    // 0) pre-split inputs to bf16 hi/lo
    {
        int n4;
        n4 = (BATCH * NN * CC) / 4;
        split_f32<<<(n4 + 255) / 256, 256>>>(node, pNhi, pNlo, n4);
        n4 = (BATCH * EE * CC) / 4;
        split_f32<<<(n4 + 255) / 256, 256>>>(hyper, pHhi, pHlo, n4);
        n4 = (CC * CC) / 4;
        split_f32<<<(n4 + 255) / 256, 256>>>(Wq, pWqhi, pWqlo, n4);
        n4 = (2 * CC * CC) / 4;
        split_f32<<<(n4 + 255) / 256, 256>>>(Wkv, pWkhi, pWklo, n4);
    }

    // 1) Q = node @ Wq^T + bq  -> bf16 hi/lo   (M=32768, N=512, K=512)
    tc_gemm_bf<<<dim3(CC / 128, (BATCH * NN) / 128, 1), 512, SMEM_T>>>(
        pNhi, pNlo, pWqhi, pWqlo, bq, nullptr, pQhi, pQlo,
        CC, CC, CC, CC, 0, 0, 0, 1.0f);

    // 2) KV = hyper @ Wkv^T + bkv -> bf16 hi/lo (M=8192, N=1024, K=512)
    tc_gemm_bf<<<dim3((2 * CC) / 128, (BATCH * EE) / 128, 1), 512, SMEM_T>>>(
        pHhi, pHlo, pWkhi, pWklo, bkv, nullptr, pKVhi, pKVlo,
        CC, CC, CC, 2 * CC, 0, 0, 0, 1.0f);

    // 3) Vt[b][c][e] = V[b][e][c]  (bf16 hi/lo)
    transpose_v_bf<<<dim3(EE / 32, CC / 32, BATCH), dim3(32, 8)>>>(pKVhi, pKVlo, pVthi, pVtlo);

    // 4) S = scale * Q @ K^T  -> bf16 hi/lo  (batched; K = first CC cols of KV, ldb=2C)
    tc_gemm_bf<<<dim3(EE / 128, NN / 128, BATCH), 512, SMEM_T>>>(
        pQhi, pQlo, pKVhi, pKVlo, nullptr, nullptr, pShi, pSlo,
        CC, CC, 2 * CC, EE,
        (size_t)NN * CC, (size_t)EE * 2 * CC, (size_t)NN * EE, scale);

    // 5) softmax rows -> bf16 hi/lo P
    softmax_rows<<<BATCH * NN, 256>>>(pShi, pSlo, pPhi, pPlo);

    // 6) out = P @ Vt^T -> fp32  (batched; M=4096, N=512, K=1024)
    tc_gemm_bf<<<dim3(CC / 128, NN / 128, BATCH), 512, SMEM_T>>>(
        pPhi, pPlo, pVthi, pVtlo, nullptr, out, nullptr, nullptr,
        EE, EE, EE, CC,
        (size_t)NN * EE, (size_t)CC * EE, (size_t)NN * CC, 1.0f);
}

// round 15
// speedup vs baseline: 1.1872x; 1.1872x over previous
#include <cuda_runtime.h>
#include <cuda_bf16.h>
#include <math.h>
#include <stdint.h>

#define BATCH 8
#define NN    4096
#define EE    1024
#define CC    512

typedef __nv_bfloat16 bf16;

// ---- scratch (device globals: allocation-free) ----
__device__ bf16  g_Nhi [(size_t)BATCH * NN * CC];
__device__ bf16  g_Nlo [(size_t)BATCH * NN * CC];
__device__ bf16  g_Hhi [(size_t)BATCH * EE * CC];
__device__ bf16  g_Hlo [(size_t)BATCH * EE * CC];
__device__ bf16  g_Wqhi[(size_t)CC * CC];
__device__ bf16  g_Wqlo[(size_t)CC * CC];
__device__ bf16  g_Wkhi[(size_t)2 * CC * CC];
__device__ bf16  g_Wklo[(size_t)2 * CC * CC];
__device__ bf16  g_Qhi [(size_t)BATCH * NN * CC];
__device__ bf16  g_Qlo [(size_t)BATCH * NN * CC];
__device__ bf16  g_KVhi[(size_t)BATCH * EE * 2 * CC];
__device__ bf16  g_KVlo[(size_t)BATCH * EE * 2 * CC];
__device__ bf16  g_Vthi[(size_t)BATCH * CC * EE];
__device__ bf16  g_Vtlo[(size_t)BATCH * CC * EE];
__device__ bf16  g_Shi [(size_t)BATCH * NN * EE];
__device__ bf16  g_Slo [(size_t)BATCH * NN * EE];
__device__ bf16  g_Phi [(size_t)BATCH * NN * EE];
__device__ bf16  g_Plo [(size_t)BATCH * NN * EE];

// ============================================================================
// helpers
// ============================================================================
static __device__ __forceinline__ uint32_t smem_u32(const void* p) {
    uint32_t a;
    asm("{ .reg .u64 t; cvta.to.shared.u64 t, %1; cvt.u32.u64 %0, t; }" : "=r"(a) : "l"(p));
    return a;
}
static __device__ __forceinline__ void mma_bf16(float* d, const uint32_t* a, const uint32_t* b) {
    asm volatile(
        "mma.sync.aligned.m16n8k16.row.col.f32.bf16.bf16.f32 "
        "{%0,%1,%2,%3}, {%4,%5,%6,%7}, {%8,%9}, {%0,%1,%2,%3};"
        : "+f"(d[0]), "+f"(d[1]), "+f"(d[2]), "+f"(d[3])
        : "r"(a[0]), "r"(a[1]), "r"(a[2]), "r"(a[3]), "r"(b[0]), "r"(b[1]));
}
static __device__ __forceinline__ void ldsm4(uint32_t* r, uint32_t addr) {
    asm volatile("ldmatrix.sync.aligned.m8n8.x4.shared.b16 {%0,%1,%2,%3}, [%4];"
        : "=r"(r[0]), "=r"(r[1]), "=r"(r[2]), "=r"(r[3]) : "r"(addr));
}
static __device__ __forceinline__ void split2(float x, float y, uint32_t& hi, uint32_t& lo) {
    bf16 hx = __float2bfloat16(x), hy = __float2bfloat16(y);
    __nv_bfloat162 h; h.x = hx; h.y = hy;
    __nv_bfloat162 l;
    l.x = __float2bfloat16(x - __bfloat162float(hx));
    l.y = __float2bfloat16(y - __bfloat162float(hy));
    hi = *reinterpret_cast<uint32_t*>(&h);
    lo = *reinterpret_cast<uint32_t*>(&l);
}
static __device__ __forceinline__ void cp16(uint32_t dst, const void* src) {
    asm volatile("cp.async.cg.shared.global [%0], [%1], 16;" :: "r"(dst), "l"(src));
}
static __device__ __forceinline__ void cp_commit() {
    asm volatile("cp.async.commit_group;" ::: "memory");
}
static __device__ __forceinline__ void cp_wait1() {
    asm volatile("cp.async.wait_group 1;" ::: "memory");
}

// ============================================================================
// elementwise fp32 -> bf16 hi/lo split (vectorized by 4)
// ============================================================================
__global__ __launch_bounds__(256) void split_f32(
    const float* __restrict__ x, bf16* __restrict__ hi, bf16* __restrict__ lo, int n4)
{
    int t = blockIdx.x * blockDim.x + threadIdx.x;
    if (t >= n4) return;
    float4 v = ((const float4*)x)[t];
    uint2 h, l;
    split2(v.x, v.y, h.x, l.x);
    split2(v.z, v.w, h.y, l.y);
    ((uint2*)hi)[t] = h;
    ((uint2*)lo)[t] = l;
}

// ============================================================================
// Tensor-core NT GEMM, pre-split bf16 hi/lo, 3-pass, fp32 acc:
//   C[m,n] = alpha * sum_k A[m,k]*B[n,k] + bias[n]
// CTA tile 128x128x32; 256 threads = 8 warps (4 m-pos x 2 n-pos), warp 32x64.
// SMEM per stage: A rows 128B = [hi 64B | lo 64B], SW128-xor swizzled; same B.
// 3-stage cp.async pipeline; 2 CTAs/SM (96KB smem, <=128 regs).
// ============================================================================
#define ARRA   (128 * 128)         // 16 KB: one operand (hi+lo interleaved)
#define STG    (2 * ARRA)          // 32 KB: A + B
#define NST    3
#define SMEM_T (NST * STG)         // 98304

__global__ __launch_bounds__(256, 2) void tc_gemm_bf(
    const bf16* __restrict__ Ahi, const bf16* __restrict__ Alo,
    const bf16* __restrict__ Bhi, const bf16* __restrict__ Blo,
    const float* __restrict__ bias,
    float* __restrict__ Cf, bf16* __restrict__ Chi, bf16* __restrict__ Clo,
    int K, int lda, int ldb, int ldc,
    size_t sA, size_t sB, size_t sC, float alpha)
{
    extern __shared__ __align__(16) unsigned char sm[];
    const uint32_t sb = smem_u32(sm);

    Ahi += (size_t)blockIdx.z * sA;  Alo += (size_t)blockIdx.z * sA;
    Bhi += (size_t)blockIdx.z * sB;  Blo += (size_t)blockIdx.z * sB;
    if (Cf)  Cf  += (size_t)blockIdx.z * sC;
    if (Chi) Chi += (size_t)blockIdx.z * sC;
    if (Clo) Clo += (size_t)blockIdx.z * sC;

    const int bm = blockIdx.y * 128;
    const int bn = blockIdx.x * 128;

    const int tid  = threadIdx.x;
    const int wid  = tid >> 5;             // 0..7
    const int lane = tid & 31;
    const int warp_m = (wid >> 1) * 32;    // 0,32,64,96
    const int warp_n = (wid & 1) * 64;     // 0,64

    // cp.async mapping: c8 = which 16B column (0-3 = hi k-cols, 4-7 = lo k-cols)
    const int c8   = tid & 7;
    const int row0 = tid >> 3;             // 0..31 (rows row0 + 32*i)
    const bf16* srcA = (c8 < 4 ? Ahi : Alo) + (size_t)(bm + row0) * lda + (c8 & 3) * 8;
    const bf16* srcB = (c8 < 4 ? Bhi : Blo) + (size_t)(bn + row0) * ldb + (c8 & 3) * 8;
    const uint32_t dst0 = (uint32_t)(row0 * 128 + ((c8 * 16) ^ ((row0 & 7) << 4)));

    const uint32_t lm_row = (uint32_t)(lane & 15);
    const uint32_t lm_k16 = (uint32_t)((lane >> 4) << 4);   // 0 or 16

    float acc[2][8][4];
    #pragma unroll
    for (int i = 0; i < 2; i++)
        #pragma unroll
        for (int j = 0; j < 8; j++)
            #pragma unroll
            for (int q = 0; q < 4; q++) acc[i][j][q] = 0.0f;

    auto cpa = [&](int st, int k0) {
        const uint32_t dA = sb + (uint32_t)(st * STG) + dst0;
        const bf16* sA = srcA + k0;
        const bf16* sB = srcB + k0;
        #pragma unroll
        for (int i = 0; i < 4; i++) {
            cp16(dA + i * 32 * 128,          sA + (size_t)i * 32 * lda);
            cp16(dA + ARRA + i * 32 * 128,   sB + (size_t)i * 32 * ldb);
        }
    };

    auto compute = [&](int st) {
        const uint32_t base = sb + (uint32_t)(st * STG);
        #pragma unroll
        for (int ks = 0; ks < 2; ks++) {
            const uint32_t kb = (uint32_t)(ks * 32) + lm_k16;   // 0,16,32,48
            uint32_t aHi[2][4], aLo[2][4];
            #pragma unroll
            for (int am = 0; am < 2; am++) {
                const uint32_t ro = (uint32_t)(warp_m + am * 16) + lm_row;
                const uint32_t sw = (ro & 7) << 4;
                ldsm4(aHi[am], base + ro * 128 + (kb ^ sw));
                ldsm4(aLo[am], base + ro * 128 + ((kb + 64) ^ sw));
            }
            #pragma unroll
            for (int bg = 0; bg < 4; bg++) {
                const uint32_t ro = (uint32_t)(warp_n + bg * 16) + lm_row;
                const uint32_t sw = (ro & 7) << 4;
                uint32_t rh[4], rl[4];
                ldsm4(rh, base + ARRA + ro * 128 + (kb ^ sw));
                ldsm4(rl, base + ARRA + ro * 128 + ((kb + 64) ^ sw));
                uint32_t bh0[2] = { rh[0], rh[2] }, bh1[2] = { rh[1], rh[3] };
                uint32_t bl0[2] = { rl[0], rl[2] }, bl1[2] = { rl[1], rl[3] };
                #pragma unroll
                for (int am = 0; am < 2; am++) {
                    float* a0 = acc[am][bg * 2 + 0];
                    mma_bf16(a0, aHi[am], bh0);
                    mma_bf16(a0, aHi[am], bl0);
                    mma_bf16(a0, aLo[am], bh0);
                    float* a1 = acc[am][bg * 2 + 1];
                    mma_bf16(a1, aHi[am], bh1);
                    mma_bf16(a1, aHi[am], bl1);
                    mma_bf16(a1, aLo[am], bh1);
                }
            }
        }
    };

    const int nch = K >> 5;
    cpa(0, 0);   cp_commit();
    cpa(1, 32);  cp_commit();
    int st = 0;
    for (int c = 0; c < nch; c++) {
        cp_wait1();
        __syncthreads();
        const int nk = c + 2;
        if (nk < nch) {
            int nst = st + 2; if (nst >= NST) nst -= NST;
            cpa(nst, nk << 5);
        }
        cp_commit();
        compute(st);
        if (++st == NST) st = 0;
    }

    // ---- epilogue ----
    const bool hb = (bias != nullptr);
    #pragma unroll
    for (int am = 0; am < 2; am++) {
        #pragma unroll
        for (int an = 0; an < 8; an++) {
            const int col = bn + warp_n + an * 8 + (lane & 3) * 2;
            float bx = 0.f, by = 0.f;
            if (hb) { bx = __ldg(&bias[col]); by = __ldg(&bias[col + 1]); }
            const int r0 = bm + warp_m + am * 16 + (lane >> 2);
            float v0x = acc[am][an][0] * alpha + bx;
            float v0y = acc[am][an][1] * alpha + by;
            float v1x = acc[am][an][2] * alpha + bx;
            float v1y = acc[am][an][3] * alpha + by;
            if (Cf) {
                *(float2*)&Cf[(size_t)r0 * ldc + col]       = make_float2(v0x, v0y);
                *(float2*)&Cf[(size_t)(r0 + 8) * ldc + col] = make_float2(v1x, v1y);
            } else {
                uint32_t h0, l0, h1, l1;
                split2(v0x, v0y, h0, l0);
                split2(v1x, v1y, h1, l1);
                *(uint32_t*)&Chi[(size_t)r0 * ldc + col]       = h0;
                *(uint32_t*)&Clo[(size_t)r0 * ldc + col]       = l0;
                *(uint32_t*)&Chi[(size_t)(r0 + 8) * ldc + col] = h1;
                *(uint32_t*)&Clo[(size_t)(r0 + 8) * ldc + col] = l1;
            }
        }
    }
}

// ============================================================================
// Transpose V half of KV (bf16 hi/lo) into Vt[b][c][e]
// ============================================================================
__global__ void transpose_v_bf(const bf16* __restrict__ KVhi, const bf16* __restrict__ KVlo,
                               bf16* __restrict__ Vthi, bf16* __restrict__ Vtlo)
{
    __shared__ bf16 th[32][33];
    __shared__ bf16 tl[32][33];
    const int b  = blockIdx.z;
    const int e0 = blockIdx.x * 32;
    const int c0 = blockIdx.y * 32;
    const int tx = threadIdx.x;
    const int ty = threadIdx.y;

    #pragma unroll
    for (int i = 0; i < 32; i += 8) {
        size_t idx = ((size_t)b * EE + e0 + ty + i) * (2 * CC) + CC + c0 + tx;
        th[ty + i][tx] = KVhi[idx];
        tl[ty + i][tx] = KVlo[idx];
    }
    __syncthreads();
    #pragma unroll
    for (int i = 0; i < 32; i += 8) {
        size_t idx = ((size_t)b * CC + c0 + ty + i) * EE + e0 + tx;
        Vthi[idx] = th[tx][ty + i];
        Vtlo[idx] = tl[tx][ty + i];
    }
}

// ============================================================================
// Row softmax over E=1024 on bf16 hi/lo logits, outputs bf16 hi/lo P.
// ============================================================================
__global__ __launch_bounds__(256) void softmax_rows(
    const bf16* __restrict__ Shi, const bf16* __restrict__ Slo,
    bf16* __restrict__ Phi, bf16* __restrict__ Plo)
{
    __shared__ float red[32];
    const size_t row = blockIdx.x;
    const int t = threadIdx.x;

    uint2 hr = ((const uint2*)(Shi + row * (size_t)EE))[t];
    uint2 lr = ((const uint2*)(Slo + row * (size_t)EE))[t];
    __nv_bfloat162 h01 = *reinterpret_cast<__nv_bfloat162*>(&hr.x);
    __nv_bfloat162 h23 = *reinterpret_cast<__nv_bfloat162*>(&hr.y);
    __nv_bfloat162 l01 = *reinterpret_cast<__nv_bfloat162*>(&lr.x);
    __nv_bfloat162 l23 = *reinterpret_cast<__nv_bfloat162*>(&lr.y);
    float4 v;
    v.x = __bfloat162float(h01.x) + __bfloat162float(l01.x);
    v.y = __bfloat162float(h01.y) + __bfloat162float(l01.y);
    v.z = __bfloat162float(h23.x) + __bfloat162float(l23.x);
    v.w = __bfloat162float(h23.y) + __bfloat162float(l23.y);

    float m = fmaxf(fmaxf(v.x, v.y), fmaxf(v.z, v.w));
    #pragma unroll
    for (int o = 16; o; o >>= 1) m = fmaxf(m, __shfl_xor_sync(0xffffffffu, m, o));
    if ((t & 31) == 0) red[t >> 5] = m;
    __syncthreads();
    if (t < 32) {
        float x = (t < 8) ? red[t] : -INFINITY;
        #pragma unroll
        for (int o = 4; o; o >>= 1) x = fmaxf(x, __shfl_xor_sync(0xffffffffu, x, o));
        if (t == 0) red[0] = x;
    }
    __syncthreads();
    m = red[0];
    __syncthreads();

    v.x = __expf(v.x - m); v.y = __expf(v.y - m);
    v.z = __expf(v.z - m); v.w = __expf(v.w - m);
    float s = v.x + v.y + v.z + v.w;
    #pragma unroll
    for (int o = 16; o; o >>= 1) s += __shfl_xor_sync(0xffffffffu, s, o);
    if ((t & 31) == 0) red[t >> 5] = s;
    __syncthreads();
    if (t < 32) {
        float x = (t < 8) ? red[t] : 0.0f;
        #pragma unroll
        for (int o = 4; o; o >>= 1) x += __shfl_xor_sync(0xffffffffu, x, o);
        if (t == 0) red[0] = x;
    }
    __syncthreads();
    const float inv = 1.0f / red[0];

    v.x *= inv; v.y *= inv; v.z *= inv; v.w *= inv;
    uint2 h, l;
    split2(v.x, v.y, h.x, l.x);
    split2(v.z, v.w, h.y, l.y);
    ((uint2*)(Phi + row * (size_t)EE))[t] = h;
    ((uint2*)(Plo + row * (size_t)EE))[t] = l;
}

// ============================================================================
// launch
// ============================================================================
extern "C" void kernel_launch(void* const* d_in, const int* in_sizes, int n_in,
                              void* d_out, int out_size)
{
    const float* node  = (const float*)d_in[0];
    const float* hyper = (const float*)d_in[1];
    const float* Wq    = (const float*)d_in[2];
    const float* bq    = (const float*)d_in[3];
    const float* Wkv   = (const float*)d_in[4];
    const float* bkv   = (const float*)d_in[5];
    float* out = (float*)d_out;

    bf16 *pNhi, *pNlo, *pHhi, *pHlo, *pWqhi, *pWqlo, *pWkhi, *pWklo;
    bf16 *pQhi, *pQlo, *pKVhi, *pKVlo, *pVthi, *pVtlo, *pPhi, *pPlo;
    bf16 *pShi, *pSlo;
    cudaGetSymbolAddress((void**)&pNhi,  g_Nhi);  cudaGetSymbolAddress((void**)&pNlo,  g_Nlo);
    cudaGetSymbolAddress((void**)&pHhi,  g_Hhi);  cudaGetSymbolAddress((void**)&pHlo,  g_Hlo);
    cudaGetSymbolAddress((void**)&pWqhi, g_Wqhi); cudaGetSymbolAddress((void**)&pWqlo, g_Wqlo);
    cudaGetSymbolAddress((void**)&pWkhi, g_Wkhi); cudaGetSymbolAddress((void**)&pWklo, g_Wklo);
    cudaGetSymbolAddress((void**)&pQhi,  g_Qhi);  cudaGetSymbolAddress((void**)&pQlo,  g_Qlo);
    cudaGetSymbolAddress((void**)&pKVhi, g_KVhi); cudaGetSymbolAddress((void**)&pKVlo, g_KVlo);
    cudaGetSymbolAddress((void**)&pVthi, g_Vthi); cudaGetSymbolAddress((void**)&pVtlo, g_Vtlo);
    cudaGetSymbolAddress((void**)&pPhi,  g_Phi);  cudaGetSymbolAddress((void**)&pPlo,  g_Plo);
    cudaGetSymbolAddress((void**)&pShi,  g_Shi);  cudaGetSymbolAddress((void**)&pSlo,  g_Slo);

    cudaFuncSetAttribute(tc_gemm_bf, cudaFuncAttributeMaxDynamicSharedMemorySize, SMEM_T);

    const float scale = 0.04419417382415922f;  // 512^-0.5

    // 0) pre-split inputs to bf16 hi/lo
    {
        int n4;
        n4 = (BATCH * NN * CC) / 4;
        split_f32<<<(n4 + 255) / 256, 256>>>(node, pNhi, pNlo, n4);
        n4 = (BATCH * EE * CC) / 4;
        split_f32<<<(n4 + 255) / 256, 256>>>(hyper, pHhi, pHlo, n4);
        n4 = (CC * CC) / 4;
        split_f32<<<(n4 + 255) / 256, 256>>>(Wq, pWqhi, pWqlo, n4);
        n4 = (2 * CC * CC) / 4;
        split_f32<<<(n4 + 255) / 256, 256>>>(Wkv, pWkhi, pWklo, n4);
    }

    // 1) Q = node @ Wq^T + bq  -> bf16 hi/lo   (M=32768, N=512, K=512)
    tc_gemm_bf<<<dim3(CC / 128, (BATCH * NN) / 128, 1), 256, SMEM_T>>>(
        pNhi, pNlo, pWqhi, pWqlo, bq, nullptr, pQhi, pQlo,
        CC, CC, CC, CC, 0, 0, 0, 1.0f);

    // 2) KV = hyper @ Wkv^T + bkv -> bf16 hi/lo (M=8192, N=1024, K=512)
    tc_gemm_bf<<<dim3((2 * CC) / 128, (BATCH * EE) / 128, 1), 256, SMEM_T>>>(
        pHhi, pHlo, pWkhi, pWklo, bkv, nullptr, pKVhi, pKVlo,
        CC, CC, CC, 2 * CC, 0, 0, 0, 1.0f);

    // 3) Vt[b][c][e] = V[b][e][c]  (bf16 hi/lo)
    transpose_v_bf<<<dim3(EE / 32, CC / 32, BATCH), dim3(32, 8)>>>(pKVhi, pKVlo, pVthi, pVtlo);

    // 4) S = scale * Q @ K^T  -> bf16 hi/lo  (batched; K = first CC cols of KV, ldb=2C)
    tc_gemm_bf<<<dim3(EE / 128, NN / 128, BATCH), 256, SMEM_T>>>(
        pQhi, pQlo, pKVhi, pKVlo, nullptr, nullptr, pShi, pSlo,
        CC, CC, 2 * CC, EE,
        (size_t)NN * CC, (size_t)EE * 2 * CC, (size_t)NN * EE, scale);

    // 5) softmax rows -> bf16 hi/lo P
    softmax_rows<<<BATCH * NN, 256>>>(pShi, pSlo, pPhi, pPlo);

    // 6) out = P @ Vt^T -> fp32  (batched; M=4096, N=512, K=1024)
    tc_gemm_bf<<<dim3(CC / 128, NN / 128, BATCH), 256, SMEM_T>>>(
        pPhi, pPlo, pVthi, pVtlo, nullptr, out, nullptr, nullptr,
        EE, EE, EE, CC,
        (size_t)NN * EE, (size_t)CC * EE, (size_t)NN * CC, 1.0f);
}

// round 16
// speedup vs baseline: 1.1949x; 1.0064x over previous
#include <cuda_runtime.h>
#include <cuda_bf16.h>
#include <math.h>
#include <stdint.h>

#define BATCH 8
#define NN    4096
#define EE    1024
#define CC    512

typedef __nv_bfloat16 bf16;

// ---- scratch (device globals: allocation-free) ----
__device__ bf16  g_Nhi [(size_t)BATCH * NN * CC];
__device__ bf16  g_Nlo [(size_t)BATCH * NN * CC];
__device__ bf16  g_Hhi [(size_t)BATCH * EE * CC];
__device__ bf16  g_Hlo [(size_t)BATCH * EE * CC];
__device__ bf16  g_Wqhi[(size_t)CC * CC];
__device__ bf16  g_Wqlo[(size_t)CC * CC];
__device__ bf16  g_Wkhi[(size_t)2 * CC * CC];
__device__ bf16  g_Wklo[(size_t)2 * CC * CC];
__device__ bf16  g_Qhi [(size_t)BATCH * NN * CC];
__device__ bf16  g_Qlo [(size_t)BATCH * NN * CC];
__device__ bf16  g_KVhi[(size_t)BATCH * EE * 2 * CC];
__device__ bf16  g_KVlo[(size_t)BATCH * EE * 2 * CC];
__device__ bf16  g_Vthi[(size_t)BATCH * CC * EE];
__device__ bf16  g_Vtlo[(size_t)BATCH * CC * EE];
__device__ bf16  g_Shi [(size_t)BATCH * NN * EE];
__device__ bf16  g_Slo [(size_t)BATCH * NN * EE];
__device__ bf16  g_Phi [(size_t)BATCH * NN * EE];
__device__ bf16  g_Plo [(size_t)BATCH * NN * EE];

// ============================================================================
// helpers
// ============================================================================
static __device__ __forceinline__ uint32_t smem_u32(const void* p) {
    uint32_t a;
    asm("{ .reg .u64 t; cvta.to.shared.u64 t, %1; cvt.u32.u64 %0, t; }" : "=r"(a) : "l"(p));
    return a;
}
static __device__ __forceinline__ void mma_bf16(float* d, const uint32_t* a, const uint32_t* b) {
    asm volatile(
        "mma.sync.aligned.m16n8k16.row.col.f32.bf16.bf16.f32 "
        "{%0,%1,%2,%3}, {%4,%5,%6,%7}, {%8,%9}, {%0,%1,%2,%3};"
        : "+f"(d[0]), "+f"(d[1]), "+f"(d[2]), "+f"(d[3])
        : "r"(a[0]), "r"(a[1]), "r"(a[2]), "r"(a[3]), "r"(b[0]), "r"(b[1]));
}
static __device__ __forceinline__ void ldsm4(uint32_t* r, uint32_t addr) {
    asm volatile("ldmatrix.sync.aligned.m8n8.x4.shared.b16 {%0,%1,%2,%3}, [%4];"
        : "=r"(r[0]), "=r"(r[1]), "=r"(r[2]), "=r"(r[3]) : "r"(addr));
}
static __device__ __forceinline__ void split2(float x, float y, uint32_t& hi, uint32_t& lo) {
    bf16 hx = __float2bfloat16(x), hy = __float2bfloat16(y);
    __nv_bfloat162 h; h.x = hx; h.y = hy;
    __nv_bfloat162 l;
    l.x = __float2bfloat16(x - __bfloat162float(hx));
    l.y = __float2bfloat16(y - __bfloat162float(hy));
    hi = *reinterpret_cast<uint32_t*>(&h);
    lo = *reinterpret_cast<uint32_t*>(&l);
}
static __device__ __forceinline__ void cp16(uint32_t dst, const void* src) {
    asm volatile("cp.async.cg.shared.global [%0], [%1], 16;" :: "r"(dst), "l"(src));
}
static __device__ __forceinline__ void cp_commit() {
    asm volatile("cp.async.commit_group;" ::: "memory");
}
static __device__ __forceinline__ void cp_wait1() {
    asm volatile("cp.async.wait_group 1;" ::: "memory");
}

// ============================================================================
// elementwise fp32 -> bf16 hi/lo split (vectorized by 4)
// ============================================================================
__global__ __launch_bounds__(256) void split_f32(
    const float* __restrict__ x, bf16* __restrict__ hi, bf16* __restrict__ lo, int n4)
{
    int t = blockIdx.x * blockDim.x + threadIdx.x;
    if (t >= n4) return;
    float4 v = ((const float4*)x)[t];
    uint2 h, l;
    split2(v.x, v.y, h.x, l.x);
    split2(v.z, v.w, h.y, l.y);
    ((uint2*)hi)[t] = h;
    ((uint2*)lo)[t] = l;
}

// ============================================================================
// Tensor-core NT GEMM, pre-split bf16 hi/lo, 3-pass, fp32 acc:
//   C[m,n] = alpha * sum_k A[m,k]*B[n,k] + bias[n]
// CTA tile 128x128x32; 128 threads = 4 warps (2x2), warp tile 64x64.
// SMEM per stage: rows of 128B = [hi 64B | lo 64B], SW128-xor swizzled.
// 3-stage cp.async pipeline; 2 CTAs/SM (96KB smem).
// ============================================================================
#define ARRA   (128 * 128)         // 16 KB: one operand (hi+lo interleaved)
#define STG    (2 * ARRA)          // 32 KB: A + B
#define NST    3
#define SMEM_T (NST * STG)         // 98304

__global__ __launch_bounds__(128, 2) void tc_gemm_bf(
    const bf16* __restrict__ Ahi, const bf16* __restrict__ Alo,
    const bf16* __restrict__ Bhi, const bf16* __restrict__ Blo,
    const float* __restrict__ bias,
    float* __restrict__ Cf, bf16* __restrict__ Chi, bf16* __restrict__ Clo,
    int K, int lda, int ldb, int ldc,
    size_t sA, size_t sB, size_t sC, float alpha)
{
    extern __shared__ __align__(16) unsigned char sm[];
    const uint32_t sb = smem_u32(sm);

    Ahi += (size_t)blockIdx.z * sA;  Alo += (size_t)blockIdx.z * sA;
    Bhi += (size_t)blockIdx.z * sB;  Blo += (size_t)blockIdx.z * sB;
    if (Cf)  Cf  += (size_t)blockIdx.z * sC;
    if (Chi) Chi += (size_t)blockIdx.z * sC;
    if (Clo) Clo += (size_t)blockIdx.z * sC;

    const int bm = blockIdx.y * 128;
    const int bn = blockIdx.x * 128;

    const int tid  = threadIdx.x;
    const int wid  = tid >> 5;             // 0..3
    const int lane = tid & 31;
    const int warp_m = (wid >> 1) * 64;    // 0,64
    const int warp_n = (wid & 1) * 64;     // 0,64

    // cp.async mapping: c8 = 16B column (0-3 = hi k-cols, 4-7 = lo k-cols)
    const int c8   = tid & 7;
    const int row0 = tid >> 3;             // 0..15 (rows row0 + 16*i, i<8)
    const bf16* srcA = (c8 < 4 ? Ahi : Alo) + (size_t)(bm + row0) * lda + (c8 & 3) * 8;
    const bf16* srcB = (c8 < 4 ? Bhi : Blo) + (size_t)(bn + row0) * ldb + (c8 & 3) * 8;
    const uint32_t dst0 = (uint32_t)(row0 * 128 + ((c8 * 16) ^ ((row0 & 7) << 4)));

    const uint32_t lm_row = (uint32_t)(lane & 15);
    const uint32_t lm_k16 = (uint32_t)((lane >> 4) << 4);   // 0 or 16

    float acc[4][8][4];
    #pragma unroll
    for (int i = 0; i < 4; i++)
        #pragma unroll
        for (int j = 0; j < 8; j++)
            #pragma unroll
            for (int q = 0; q < 4; q++) acc[i][j][q] = 0.0f;

    auto cpa = [&](int st, int k0) {
        const uint32_t dA = sb + (uint32_t)(st * STG) + dst0;
        const bf16* sA = srcA + k0;
        const bf16* sB = srcB + k0;
        #pragma unroll
        for (int i = 0; i < 8; i++) {
            cp16(dA + i * 16 * 128,         sA + (size_t)i * 16 * lda);
            cp16(dA + ARRA + i * 16 * 128,  sB + (size_t)i * 16 * ldb);
        }
    };

    auto compute = [&](int st) {
        const uint32_t base = sb + (uint32_t)(st * STG);
        #pragma unroll
        for (int ks = 0; ks < 2; ks++) {
            const uint32_t kb = (uint32_t)(ks * 32) + lm_k16;   // 0,16,32,48
            uint32_t aHi[4][4], aLo[4][4];
            #pragma unroll
            for (int am = 0; am < 4; am++) {
                const uint32_t ro = (uint32_t)(warp_m + am * 16) + lm_row;
                const uint32_t sw = (ro & 7) << 4;
                ldsm4(aHi[am], base + ro * 128 + (kb ^ sw));
                ldsm4(aLo[am], base + ro * 128 + ((kb + 64) ^ sw));
            }
            #pragma unroll
            for (int bg = 0; bg < 4; bg++) {
                const uint32_t ro = (uint32_t)(warp_n + bg * 16) + lm_row;
                const uint32_t sw = (ro & 7) << 4;
                uint32_t rh[4], rl[4];
                ldsm4(rh, base + ARRA + ro * 128 + (kb ^ sw));
                ldsm4(rl, base + ARRA + ro * 128 + ((kb + 64) ^ sw));
                uint32_t bh0[2] = { rh[0], rh[2] }, bh1[2] = { rh[1], rh[3] };
                uint32_t bl0[2] = { rl[0], rl[2] }, bl1[2] = { rl[1], rl[3] };
                #pragma unroll
                for (int am = 0; am < 4; am++) {
                    float* a0 = acc[am][bg * 2 + 0];
                    mma_bf16(a0, aHi[am], bh0);
                    mma_bf16(a0, aHi[am], bl0);
                    mma_bf16(a0, aLo[am], bh0);
                    float* a1 = acc[am][bg * 2 + 1];
                    mma_bf16(a1, aHi[am], bh1);
                    mma_bf16(a1, aHi[am], bl1);
                    mma_bf16(a1, aLo[am], bh1);
                }
            }
        }
    };

    const int nch = K >> 5;
    cpa(0, 0);   cp_commit();
    cpa(1, 32);  cp_commit();
    int st = 0;
    for (int c = 0; c < nch; c++) {
        cp_wait1();
        __syncthreads();
        const int nk = c + 2;
        if (nk < nch) {
            int nst = st + 2; if (nst >= NST) nst -= NST;
            cpa(nst, nk << 5);
        }
        cp_commit();
        compute(st);
        if (++st == NST) st = 0;
    }

    // ---- epilogue ----
    const bool hb = (bias != nullptr);
    #pragma unroll
    for (int am = 0; am < 4; am++) {
        #pragma unroll
        for (int an = 0; an < 8; an++) {
            const int col = bn + warp_n + an * 8 + (lane & 3) * 2;
            float bx = 0.f, by = 0.f;
            if (hb) { bx = __ldg(&bias[col]); by = __ldg(&bias[col + 1]); }
            const int r0 = bm + warp_m + am * 16 + (lane >> 2);
            float v0x = acc[am][an][0] * alpha + bx;
            float v0y = acc[am][an][1] * alpha + by;
            float v1x = acc[am][an][2] * alpha + bx;
            float v1y = acc[am][an][3] * alpha + by;
            if (Cf) {
                *(float2*)&Cf[(size_t)r0 * ldc + col]       = make_float2(v0x, v0y);
                *(float2*)&Cf[(size_t)(r0 + 8) * ldc + col] = make_float2(v1x, v1y);
            } else {
                uint32_t h0, l0, h1, l1;
                split2(v0x, v0y, h0, l0);
                split2(v1x, v1y, h1, l1);
                *(uint32_t*)&Chi[(size_t)r0 * ldc + col]       = h0;
                *(uint32_t*)&Clo[(size_t)r0 * ldc + col]       = l0;
                *(uint32_t*)&Chi[(size_t)(r0 + 8) * ldc + col] = h1;
                *(uint32_t*)&Clo[(size_t)(r0 + 8) * ldc + col] = l1;
            }
        }
    }
}

// ============================================================================
// Transpose V half of KV (bf16 hi/lo) into Vt[b][c][e]
// ============================================================================
__global__ void transpose_v_bf(const bf16* __restrict__ KVhi, const bf16* __restrict__ KVlo,
                               bf16* __restrict__ Vthi, bf16* __restrict__ Vtlo)
{
    __shared__ bf16 th[32][33];
    __shared__ bf16 tl[32][33];
    const int b  = blockIdx.z;
    const int e0 = blockIdx.x * 32;
    const int c0 = blockIdx.y * 32;
    const int tx = threadIdx.x;
    const int ty = threadIdx.y;

    #pragma unroll
    for (int i = 0; i < 32; i += 8) {
        size_t idx = ((size_t)b * EE + e0 + ty + i) * (2 * CC) + CC + c0 + tx;
        th[ty + i][tx] = KVhi[idx];
        tl[ty + i][tx] = KVlo[idx];
    }
    __syncthreads();
    #pragma unroll
    for (int i = 0; i < 32; i += 8) {
        size_t idx = ((size_t)b * CC + c0 + ty + i) * EE + e0 + tx;
        Vthi[idx] = th[tx][ty + i];
        Vtlo[idx] = tl[tx][ty + i];
    }
}

// ============================================================================
// Row softmax over E=1024 on bf16 hi/lo logits, outputs bf16 hi/lo P.
// ============================================================================
__global__ __launch_bounds__(256) void softmax_rows(
    const bf16* __restrict__ Shi, const bf16* __restrict__ Slo,
    bf16* __restrict__ Phi, bf16* __restrict__ Plo)
{
    __shared__ float red[32];
    const size_t row = blockIdx.x;
    const int t = threadIdx.x;

    uint2 hr = ((const uint2*)(Shi + row * (size_t)EE))[t];
    uint2 lr = ((const uint2*)(Slo + row * (size_t)EE))[t];
    __nv_bfloat162 h01 = *reinterpret_cast<__nv_bfloat162*>(&hr.x);
    __nv_bfloat162 h23 = *reinterpret_cast<__nv_bfloat162*>(&hr.y);
    __nv_bfloat162 l01 = *reinterpret_cast<__nv_bfloat162*>(&lr.x);
    __nv_bfloat162 l23 = *reinterpret_cast<__nv_bfloat162*>(&lr.y);
    float4 v;
    v.x = __bfloat162float(h01.x) + __bfloat162float(l01.x);
    v.y = __bfloat162float(h01.y) + __bfloat162float(l01.y);
    v.z = __bfloat162float(h23.x) + __bfloat162float(l23.x);
    v.w = __bfloat162float(h23.y) + __bfloat162float(l23.y);

    float m = fmaxf(fmaxf(v.x, v.y), fmaxf(v.z, v.w));
    #pragma unroll
    for (int o = 16; o; o >>= 1) m = fmaxf(m, __shfl_xor_sync(0xffffffffu, m, o));
    if ((t & 31) == 0) red[t >> 5] = m;
    __syncthreads();
    if (t < 32) {
        float x = (t < 8) ? red[t] : -INFINITY;
        #pragma unroll
        for (int o = 4; o; o >>= 1) x = fmaxf(x, __shfl_xor_sync(0xffffffffu, x, o));
        if (t == 0) red[0] = x;
    }
    __syncthreads();
    m = red[0];
    __syncthreads();

    v.x = __expf(v.x - m); v.y = __expf(v.y - m);
    v.z = __expf(v.z - m); v.w = __expf(v.w - m);
    float s = v.x + v.y + v.z + v.w;
    #pragma unroll
    for (int o = 16; o; o >>= 1) s += __shfl_xor_sync(0xffffffffu, s, o);
    if ((t & 31) == 0) red[t >> 5] = s;
    __syncthreads();
    if (t < 32) {
        float x = (t < 8) ? red[t] : 0.0f;
        #pragma unroll
        for (int o = 4; o; o >>= 1) x += __shfl_xor_sync(0xffffffffu, x, o);
        if (t == 0) red[0] = x;
    }
    __syncthreads();
    const float inv = 1.0f / red[0];

    v.x *= inv; v.y *= inv; v.z *= inv; v.w *= inv;
    uint2 h, l;
    split2(v.x, v.y, h.x, l.x);
    split2(v.z, v.w, h.y, l.y);
    ((uint2*)(Phi + row * (size_t)EE))[t] = h;
    ((uint2*)(Plo + row * (size_t)EE))[t] = l;
}

// ============================================================================
// launch
// ============================================================================
extern "C" void kernel_launch(void* const* d_in, const int* in_sizes, int n_in,
                              void* d_out, int out_size)
{
    const float* node  = (const float*)d_in[0];
    const float* hyper = (const float*)d_in[1];
    const float* Wq    = (const float*)d_in[2];
    const float* bq    = (const float*)d_in[3];
    const float* Wkv   = (const float*)d_in[4];
    const float* bkv   = (const float*)d_in[5];
    float* out = (float*)d_out;

    bf16 *pNhi, *pNlo, *pHhi, *pHlo, *pWqhi, *pWqlo, *pWkhi, *pWklo;
    bf16 *pQhi, *pQlo, *pKVhi, *pKVlo, *pVthi, *pVtlo, *pPhi, *pPlo;
    bf16 *pShi, *pSlo;
    cudaGetSymbolAddress((void**)&pNhi,  g_Nhi);  cudaGetSymbolAddress((void**)&pNlo,  g_Nlo);
    cudaGetSymbolAddress((void**)&pHhi,  g_Hhi);  cudaGetSymbolAddress((void**)&pHlo,  g_Hlo);
    cudaGetSymbolAddress((void**)&pWqhi, g_Wqhi); cudaGetSymbolAddress((void**)&pWqlo, g_Wqlo);
    cudaGetSymbolAddress((void**)&pWkhi, g_Wkhi); cudaGetSymbolAddress((void**)&pWklo, g_Wklo);
    cudaGetSymbolAddress((void**)&pQhi,  g_Qhi);  cudaGetSymbolAddress((void**)&pQlo,  g_Qlo);
    cudaGetSymbolAddress((void**)&pKVhi, g_KVhi); cudaGetSymbolAddress((void**)&pKVlo, g_KVlo);
    cudaGetSymbolAddress((void**)&pVthi, g_Vthi); cudaGetSymbolAddress((void**)&pVtlo, g_Vtlo);
    cudaGetSymbolAddress((void**)&pPhi,  g_Phi);  cudaGetSymbolAddress((void**)&pPlo,  g_Plo);
    cudaGetSymbolAddress((void**)&pShi,  g_Shi);  cudaGetSymbolAddress((void**)&pSlo,  g_Slo);

    cudaFuncSetAttribute(tc_gemm_bf, cudaFuncAttributeMaxDynamicSharedMemorySize, SMEM_T);

    const float scale = 0.04419417382415922f;  // 512^-0.5

    // 0) pre-split inputs to bf16 hi/lo
    {
        int n4;
        n4 = (BATCH * NN * CC) / 4;
        split_f32<<<(n4 + 255) / 256, 256>>>(node, pNhi, pNlo, n4);
        n4 = (BATCH * EE * CC) / 4;
        split_f32<<<(n4 + 255) / 256, 256>>>(hyper, pHhi, pHlo, n4);
        n4 = (CC * CC) / 4;
        split_f32<<<(n4 + 255) / 256, 256>>>(Wq, pWqhi, pWqlo, n4);
        n4 = (2 * CC * CC) / 4;
        split_f32<<<(n4 + 255) / 256, 256>>>(Wkv, pWkhi, pWklo, n4);
    }

    // 1) Q = node @ Wq^T + bq  -> bf16 hi/lo   (M=32768, N=512, K=512)
    tc_gemm_bf<<<dim3(CC / 128, (BATCH * NN) / 128, 1), 128, SMEM_T>>>(
        pNhi, pNlo, pWqhi, pWqlo, bq, nullptr, pQhi, pQlo,
        CC, CC, CC, CC, 0, 0, 0, 1.0f);

    // 2) KV = hyper @ Wkv^T + bkv -> bf16 hi/lo (M=8192, N=1024, K=512)
    tc_gemm_bf<<<dim3((2 * CC) / 128, (BATCH * EE) / 128, 1), 128, SMEM_T>>>(
        pHhi, pHlo, pWkhi, pWklo, bkv, nullptr, pKVhi, pKVlo,
        CC, CC, CC, 2 * CC, 0, 0, 0, 1.0f);

    // 3) Vt[b][c][e] = V[b][e][c]  (bf16 hi/lo)
    transpose_v_bf<<<dim3(EE / 32, CC / 32, BATCH), dim3(32, 8)>>>(pKVhi, pKVlo, pVthi, pVtlo);

    // 4) S = scale * Q @ K^T  -> bf16 hi/lo  (batched; K = first CC cols of KV, ldb=2C)
    tc_gemm_bf<<<dim3(EE / 128, NN / 128, BATCH), 128, SMEM_T>>>(
        pQhi, pQlo, pKVhi, pKVlo, nullptr, nullptr, pShi, pSlo,
        CC, CC, 2 * CC, EE,
        (size_t)NN * CC, (size_t)EE * 2 * CC, (size_t)NN * EE, scale);

    // 5) softmax rows -> bf16 hi/lo P
    softmax_rows<<<BATCH * NN, 256>>>(pShi, pSlo, pPhi, pPlo);

    // 6) out = P @ Vt^T -> fp32  (batched; M=4096, N=512, K=1024)
    tc_gemm_bf<<<dim3(CC / 128, NN / 128, BATCH), 128, SMEM_T>>>(
        pPhi, pPlo, pVthi, pVtlo, nullptr, out, nullptr, nullptr,
        EE, EE, EE, CC,
        (size_t)NN * EE, (size_t)CC * EE, (size_t)NN * CC, 1.0f);
}